// round 3
// baseline (speedup 1.0000x reference)
#include <cuda_runtime.h>

#define NN 20000
#define EE 320000
using u64 = unsigned long long;

__device__ float g_x[NN*3];
__device__ float g_h[NN*64];
__device__ float g_A[NN*64];
__device__ float g_B[NN*64];
__device__ float g_agg[NN*64];
__device__ float g_xacc[NN*3];
__device__ float g_cnt[NN];
__device__ float g_invc[NN];

__device__ __forceinline__ float silu(float v){ return __fdividef(v, 1.f+__expf(-v)); }
__device__ __forceinline__ u64 pack2(float x){ u64 r; asm("mov.b64 %0,{%1,%1};":"=l"(r):"f"(x)); return r; }
__device__ __forceinline__ u64 ffma2(u64 a,u64 b,u64 c){ u64 d; asm("fma.rn.f32x2 %0,%1,%2,%3;":"=l"(d):"l"(a),"l"(b),"l"(c)); return d; }
__device__ __forceinline__ float2 unpk(u64 a){ float x,y; asm("mov.b64 {%0,%1},%2;":"=f"(x),"=f"(y):"l"(a)); return make_float2(x,y); }

// Warp-cooperative 8-row x W[K,64] matvec. q=lane&15 -> out cols [4q,4q+4),
// g2=lane>>4 -> rows g2*4..g2*4+3. vb = smem base of this group's row 0
// (stride ST words). acc[2r]=cols(4q,4q+1), acc[2r+1]=cols(4q+2,4q+3) of row r.
template<int K>
__device__ __forceinline__ void mv8(const float* vb,int ST,const float* W,int q,u64* acc){
#pragma unroll 4
  for(int k4=0;k4<K;k4+=4){
    float4 a0=*(const float4*)(vb+0*ST+k4);
    float4 a1=*(const float4*)(vb+1*ST+k4);
    float4 a2=*(const float4*)(vb+2*ST+k4);
    float4 a3=*(const float4*)(vb+3*ST+k4);
    float va[4][4]={{a0.x,a0.y,a0.z,a0.w},{a1.x,a1.y,a1.z,a1.w},
                    {a2.x,a2.y,a2.z,a2.w},{a3.x,a3.y,a3.z,a3.w}};
#pragma unroll
    for(int j=0;j<4;j++){
      ulonglong2 w=*(const ulonglong2*)(W+(k4+j)*64+q*4);
#pragma unroll
      for(int r=0;r<4;r++){
        u64 p=pack2(va[r][j]);
        acc[2*r]  =ffma2(w.x,p,acc[2*r]);
        acc[2*r+1]=ffma2(w.y,p,acc[2*r+1]);
      }
    }
  }
}
__device__ __forceinline__ void acc_init(u64* acc,const float* sb,int q){
  u64 b01=((const u64*)sb)[q*2], b23=((const u64*)sb)[q*2+1];
#pragma unroll
  for(int r=0;r<4;r++){ acc[2*r]=b01; acc[2*r+1]=b23; }
}

__global__ void k_zero(){
  int i=blockIdx.x*blockDim.x+threadIdx.x;
  if(i<NN*64) g_agg[i]=0.f;
  if(i<NN*3)  g_xacc[i]=0.f;
  if(i<NN)    g_cnt[i]=0.f;
}
__global__ void k_count(const int* __restrict__ erow){
  int e=blockIdx.x*blockDim.x+threadIdx.x;
  if(e<EE) atomicAdd(&g_cnt[erow[e]],1.f);
}

// h0 = h16@Wi+bi ; copy x ; invc
__global__ void __launch_bounds__(256) k_embed(
    const float* __restrict__ h16,const float* __restrict__ xin,
    const float* __restrict__ Wi,const float* __restrict__ bi){
  extern __shared__ float sm[];
  float* sWi=sm; float* sbi=sm+1024;        // 16*64 , 64
  const int tid=threadIdx.x,wid=tid>>5,lane=tid&31,q=lane&15,g2=lane>>4;
  const int ST=20; float* vb=sm+1088+wid*(8*ST);
  for(int i=tid;i<256;i+=256) ((float4*)sWi)[i]=((const float4*)Wi)[i];
  if(tid<64) sbi[tid]=bi[tid];
  int nbase=blockIdx.x*64+wid*8;
#pragma unroll
  for(int t=0;t<4;t++){
    int e=t*2+g2,n=nbase+e;
    if(q<4){
      float4 v=make_float4(0,0,0,0);
      if(n<NN) v=*(const float4*)&h16[n*16+q*4];
      *(float4*)&vb[e*ST+q*4]=v;
    }
  }
  if(lane<8){ int n=nbase+lane; if(n<NN) g_invc[n]=__fdividef(1.f,fmaxf(g_cnt[n],1.f)); }
  if(lane<24){ int e=lane/3,d=lane-3*(lane/3),n=nbase+e; if(n<NN) g_x[n*3+d]=xin[n*3+d]; }
  __syncthreads();
  u64 acc[8]; acc_init(acc,sbi,q);
  mv8<16>(vb+g2*4*ST,ST,sWi,q,acc);
#pragma unroll
  for(int r=0;r<4;r++){
    int n=nbase+g2*4+r;
    if(n<NN){
      float2 lo=unpk(acc[2*r]),hi=unpk(acc[2*r+1]);
      *(float4*)&g_h[n*64+q*4]=make_float4(lo.x,lo.y,hi.x,hi.y);
    }
  }
}

// per-layer precompute: A=h@EA+eb, B=h@EB
__global__ void __launch_bounds__(256) k_AB(
    const float* __restrict__ EA,const float* __restrict__ eb,
    const float* __restrict__ EB){
  extern __shared__ float sm[];
  float* sEA=sm; float* sEB=sm+4096; float* seb=sm+8192;
  const int tid=threadIdx.x,wid=tid>>5,lane=tid&31,q=lane&15,g2=lane>>4;
  const int ST=68; float* vb=sm+8256+wid*(8*ST);
  for(int i=tid;i<1024;i+=256){ ((float4*)sEA)[i]=((const float4*)EA)[i]; ((float4*)sEB)[i]=((const float4*)EB)[i]; }
  if(tid<64) seb[tid]=eb[tid];
  int nbase=blockIdx.x*64+wid*8;
#pragma unroll
  for(int t=0;t<4;t++){
    int e=t*2+g2,n=nbase+e;
    float4 v=make_float4(0,0,0,0);
    if(n<NN) v=*(const float4*)&g_h[n*64+q*4];
    *(float4*)&vb[e*ST+q*4]=v;
  }
  __syncthreads();
  u64 aA[8],aB[8]; acc_init(aA,seb,q);
#pragma unroll
  for(int i=0;i<8;i++) aB[i]=0ull;
  mv8<64>(vb+g2*4*ST,ST,sEA,q,aA);
  mv8<64>(vb+g2*4*ST,ST,sEB,q,aB);
#pragma unroll
  for(int r=0;r<4;r++){
    int n=nbase+g2*4+r;
    if(n<NN){
      float2 lo=unpk(aA[2*r]),hi=unpk(aA[2*r+1]);
      *(float4*)&g_A[n*64+q*4]=make_float4(lo.x,lo.y,hi.x,hi.y);
      lo=unpk(aB[2*r]); hi=unpk(aB[2*r+1]);
      *(float4*)&g_B[n*64+q*4]=make_float4(lo.x,lo.y,hi.x,hi.y);
    }
  }
}

// edge kernel: 8 edges/warp, 64 edges/block (EE%64==0)
__global__ void __launch_bounds__(256) k_edge(
    const int* __restrict__ erow,const int* __restrict__ ecol,
    const float* __restrict__ w1c,const float* __restrict__ W2,
    const float* __restrict__ b2,const float* __restrict__ CW1,
    const float* __restrict__ cb1,const float* __restrict__ cw2){
  extern __shared__ float sm[];
  float* sW2=sm; float* sCW1=sm+4096;
  float* sw1c=sm+8192; float* sb2=sm+8256; float* scb1=sm+8320; float* scw2=sm+8384;
  const int tid=threadIdx.x,wid=tid>>5,lane=tid&31,q=lane&15,g2=lane>>4;
  float* wsm=sm+8448+wid*1152;
  float* m1b=wsm; float* mb=wsm+544; float* dfb=wsm+1088;
  float* rdb=wsm+1112; float* icb=wsm+1120;
  int* rwb=(int*)(wsm+1128); int* clb=(int*)(wsm+1136);
  for(int i=tid;i<1024;i+=256){ ((float4*)sW2)[i]=((const float4*)W2)[i]; ((float4*)sCW1)[i]=((const float4*)CW1)[i]; }
  if(tid<64){ sw1c[tid]=w1c[tid]; sb2[tid]=b2[tid]; scb1[tid]=cb1[tid]; scw2[tid]=cw2[tid]; }
  int ebase=blockIdx.x*64+wid*8;
  if(lane<8){
    int e=ebase+lane,r=erow[e],c=ecol[e];
    rwb[lane]=r; clb[lane]=c;
    float dx=g_x[r*3]-g_x[c*3],dy=g_x[r*3+1]-g_x[c*3+1],dz=g_x[r*3+2]-g_x[c*3+2];
    dfb[lane*3]=dx; dfb[lane*3+1]=dy; dfb[lane*3+2]=dz;
    rdb[lane]=dx*dx+dy*dy+dz*dz; icb[lane]=g_invc[r];
  }
  __syncthreads();
  { // phase1: silu(A[r]+B[c]+rad*w1c)
    float4 wc=*(const float4*)&sw1c[q*4];
#pragma unroll
    for(int t=0;t<4;t++){
      int e=t*2+g2;
      float4 av=*(const float4*)&g_A[rwb[e]*64+q*4];
      float4 bv=*(const float4*)&g_B[clb[e]*64+q*4];
      float rad=rdb[e];
      *(float4*)&m1b[e*68+q*4]=make_float4(
        silu(av.x+bv.x+rad*wc.x), silu(av.y+bv.y+rad*wc.y),
        silu(av.z+bv.z+rad*wc.z), silu(av.w+bv.w+rad*wc.w));
    }
  }
  __syncwarp();
  u64 acc[8]; acc_init(acc,sb2,q);
  mv8<64>(m1b+g2*4*68,68,sW2,q,acc);
#pragma unroll
  for(int r=0;r<4;r++){
    int e=g2*4+r;
    float2 lo=unpk(acc[2*r]),hi=unpk(acc[2*r+1]);
    float m0=silu(lo.x),m1=silu(lo.y),m2=silu(hi.x),m3=silu(hi.y);
    *(float4*)&mb[e*68+q*4]=make_float4(m0,m1,m2,m3);
    float* ap=&g_agg[rwb[e]*64+q*4];
    asm volatile("red.global.add.v4.f32 [%0],{%1,%2,%3,%4};"
                 ::"l"(ap),"f"(m0),"f"(m1),"f"(m2),"f"(m3):"memory");
  }
  __syncwarp();
  acc_init(acc,scb1,q);
  mv8<64>(mb+g2*4*68,68,sCW1,q,acc);
  float4 c4=*(const float4*)&scw2[q*4];
  float s[4];
#pragma unroll
  for(int r=0;r<4;r++){
    float2 lo=unpk(acc[2*r]),hi=unpk(acc[2*r+1]);
    s[r]=silu(lo.x)*c4.x+silu(lo.y)*c4.y+silu(hi.x)*c4.z+silu(hi.y)*c4.w;
  }
#pragma unroll
  for(int off=1;off<16;off<<=1){
#pragma unroll
    for(int r=0;r<4;r++) s[r]+=__shfl_xor_sync(0xffffffffu,s[r],off);
  }
  if(q<12){
    int j=q/3,d=q-3*j,e=g2*4+j;
    atomicAdd(&g_xacc[rwb[e]*3+d], dfb[e*3+d]*s[j]*icb[e]);
  }
}

// node kernel: x+=xacc; t=silu([h|agg]@NW1+nb1); h+=t@NW2+nb2; rezero agg/xacc
__global__ void __launch_bounds__(256) k_node(
    const float* __restrict__ NW1,const float* __restrict__ nb1,
    const float* __restrict__ NW2,const float* __restrict__ nb2){
  extern __shared__ float sm[];
  float* sNW1=sm; float* sNW2=sm+8192; float* snb1=sm+12288; float* snb2=sm+12352;
  const int tid=threadIdx.x,wid=tid>>5,lane=tid&31,q=lane&15,g2=lane>>4;
  const int ST=132; float* vb=sm+12416+wid*(8*ST);
  for(int i=tid;i<2048;i+=256) ((float4*)sNW1)[i]=((const float4*)NW1)[i];
  for(int i=tid;i<1024;i+=256) ((float4*)sNW2)[i]=((const float4*)NW2)[i];
  if(tid<64){ snb1[tid]=nb1[tid]; snb2[tid]=nb2[tid]; }
  int nbase=blockIdx.x*64+wid*8;
#pragma unroll
  for(int t=0;t<4;t++){
    int e=t*2+g2,n=nbase+e;
    float4 h4=make_float4(0,0,0,0),a4=make_float4(0,0,0,0);
    if(n<NN){
      h4=*(const float4*)&g_h[n*64+q*4];
      a4=*(const float4*)&g_agg[n*64+q*4];
      *(float4*)&g_agg[n*64+q*4]=make_float4(0,0,0,0);
    }
    *(float4*)&vb[e*ST+q*4]=h4;
    *(float4*)&vb[e*ST+64+q*4]=a4;
  }
  if(lane<24){
    int e=lane/3,d=lane-3*(lane/3),n=nbase+e;
    if(n<NN){ g_x[n*3+d]+=g_xacc[n*3+d]; g_xacc[n*3+d]=0.f; }
  }
  __syncthreads();
  u64 acc[8]; acc_init(acc,snb1,q);
  mv8<128>(vb+g2*4*ST,ST,sNW1,q,acc);
  __syncwarp();
#pragma unroll
  for(int r=0;r<4;r++){
    int e=g2*4+r;
    float2 lo=unpk(acc[2*r]),hi=unpk(acc[2*r+1]);
    *(float4*)&vb[e*ST+q*4]=make_float4(silu(lo.x),silu(lo.y),silu(hi.x),silu(hi.y));
  }
  __syncwarp();
  acc_init(acc,snb2,q);
  mv8<64>(vb+g2*4*ST,ST,sNW2,q,acc);
#pragma unroll
  for(int r=0;r<4;r++){
    int n=nbase+g2*4+r;
    if(n<NN){
      float4 h4=*(const float4*)&g_h[n*64+q*4];
      float2 lo=unpk(acc[2*r]),hi=unpk(acc[2*r+1]);
      *(float4*)&g_h[n*64+q*4]=make_float4(h4.x+lo.x,h4.y+lo.y,h4.z+hi.x,h4.w+hi.y);
    }
  }
}

// out: h@Wo+bo -> d_out[0..N*64), x -> d_out[N*64..)
__global__ void __launch_bounds__(256) k_out(
    const float* __restrict__ Wo,const float* __restrict__ bo,float* __restrict__ outp){
  extern __shared__ float sm[];
  float* sWo=sm; float* sbo=sm+4096;
  const int tid=threadIdx.x,wid=tid>>5,lane=tid&31,q=lane&15,g2=lane>>4;
  const int ST=68; float* vb=sm+4160+wid*(8*ST);
  for(int i=tid;i<1024;i+=256) ((float4*)sWo)[i]=((const float4*)Wo)[i];
  if(tid<64) sbo[tid]=bo[tid];
  int nbase=blockIdx.x*64+wid*8;
#pragma unroll
  for(int t=0;t<4;t++){
    int e=t*2+g2,n=nbase+e;
    float4 v=make_float4(0,0,0,0);
    if(n<NN) v=*(const float4*)&g_h[n*64+q*4];
    *(float4*)&vb[e*ST+q*4]=v;
  }
  if(lane<24){
    int e=lane/3,d=lane-3*(lane/3),n=nbase+e;
    if(n<NN) outp[NN*64+n*3+d]=g_x[n*3+d];
  }
  __syncthreads();
  u64 acc[8]; acc_init(acc,sbo,q);
  mv8<64>(vb+g2*4*ST,ST,sWo,q,acc);
#pragma unroll
  for(int r=0;r<4;r++){
    int n=nbase+g2*4+r;
    if(n<NN){
      float2 lo=unpk(acc[2*r]),hi=unpk(acc[2*r+1]);
      *(float4*)&outp[n*64+q*4]=make_float4(lo.x,lo.y,hi.x,hi.y);
    }
  }
}

extern "C" void kernel_launch(void* const* d_in,const int* in_sizes,int n_in,
                              void* d_out,int out_size){
  const float* h16=(const float*)d_in[0];
  const float* xin=(const float*)d_in[1];
  const int*   ei =(const int*  )d_in[2];
  const float* Wi =(const float*)d_in[3];
  const float* bi =(const float*)d_in[4];
  const float* ew1=(const float*)d_in[5];
  const float* eb1=(const float*)d_in[6];
  const float* ew2=(const float*)d_in[7];
  const float* eb2=(const float*)d_in[8];
  const float* cw1=(const float*)d_in[9];
  const float* cb1=(const float*)d_in[10];
  const float* cw2=(const float*)d_in[11];
  const float* nw1=(const float*)d_in[12];
  const float* nb1=(const float*)d_in[13];
  const float* nw2=(const float*)d_in[14];
  const float* nb2=(const float*)d_in[15];
  const float* Wo =(const float*)d_in[16];
  const float* bo =(const float*)d_in[17];
  float* outp=(float*)d_out;
  const int* erow=ei; const int* ecol=ei+EE;

  const int SM_EMBED=(1088+8*8*20)*4;
  const int SM_AB   =(8256+8*8*68)*4;
  const int SM_EDGE =(8448+8*1152)*4;
  const int SM_NODE =(12416+8*8*132)*4;
  const int SM_OUT  =(4160+8*8*68)*4;
  cudaFuncSetAttribute(k_AB,  cudaFuncAttributeMaxDynamicSharedMemorySize,SM_AB);
  cudaFuncSetAttribute(k_edge,cudaFuncAttributeMaxDynamicSharedMemorySize,SM_EDGE);
  cudaFuncSetAttribute(k_node,cudaFuncAttributeMaxDynamicSharedMemorySize,SM_NODE);

  const int NB=(NN+63)/64;           // 313
  k_zero<<<(NN*64+255)/256,256>>>();
  k_count<<<(EE+255)/256,256>>>(erow);
  k_embed<<<NB,256,SM_EMBED>>>(h16,xin,Wi,bi);
  for(int l=0;l<4;l++){
    const float* EA=ew1+l*129*64;
    k_AB<<<NB,256,SM_AB>>>(EA,eb1+l*64,EA+64*64);
    k_edge<<<EE/64,256,SM_EDGE>>>(erow,ecol,EA+128*64,ew2+l*4096,eb2+l*64,
                                  cw1+l*4096,cb1+l*64,cw2+l*64);
    k_node<<<NB,256,SM_NODE>>>(nw1+l*128*64,nb1+l*64,nw2+l*4096,nb2+l*64);
  }
  k_out<<<NB,256,SM_OUT>>>(Wo,bo,outp);
}